// round 12
// baseline (speedup 1.0000x reference)
#include <cuda_runtime.h>
#include <cuda_bf16.h>
#include <cstdint>

// Problem dims
#define BATCH 256
#define HID   512
#define SEQ   250
#define INDIM 5

// Persistent tiling: 128 CTAs = 2 batch groups (M=128) x 64 hidden slices (HC=8 -> N=32 gate cols)
#define GRID  128
#define NT    256          // 8 warps; each warp owns one m16 band, all 4 n8 tiles
#define HC 8
#define NC 32              // 4 gates * HC

// SMEM pitches (bf16 elements). 520*2B = 1040B, 1040 mod 128 = 16 -> ldmatrix conflict-free
#define APITCH 520
#define BP     520

#define SA_BYTES  (128 * APITCH * 2)           // 133120
#define SBH_BYTES (NC * BP * 2)                // 33280 (W_hh hi)
#define SBL_BYTES (NC * BP * 2)                // 33280 (W_hh lo)
#define SX_BYTES  (128 * INDIM * 4)            // 2560
#define SWIH_BYTES (NC * INDIM * 4)            // 640
#define SBIAS_BYTES (NC * 4)                   // 128
#define SMEM_BYTES (SA_BYTES + SBH_BYTES + SBL_BYTES + SX_BYTES + SWIH_BYTES + SBIAS_BYTES)

// Persistent state (device globals: no allocation in kernel_launch)
__device__ __nv_bfloat16 g_h[2][BATCH * HID];
__device__ unsigned g_flags[GRID];             // distributed barrier flags (one per CTA)

__device__ __forceinline__ float fast_ex2(float x) {
    float y; asm("ex2.approx.f32 %0, %1;" : "=f"(y) : "f"(x)); return y;
}
__device__ __forceinline__ float fast_rcp(float x) {
    float y; asm("rcp.approx.f32 %0, %1;" : "=f"(y) : "f"(x)); return y;
}
// sigmoid(x) = 1/(1+2^(-x*log2e)); rel err ~1e-6
__device__ __forceinline__ float fast_sig(float x) {
    return fast_rcp(1.0f + fast_ex2(-1.4426950408889634f * x));
}
// tanh(x) = 2*sigmoid(2x)-1
__device__ __forceinline__ float fast_tanh(float x) {
    float s = fast_rcp(1.0f + fast_ex2(-2.8853900817779268f * x));
    return fmaf(2.0f, s, -1.0f);
}

__device__ __forceinline__ void mma_bf16(float* c, const unsigned* a, unsigned b0, unsigned b1) {
    asm volatile(
        "mma.sync.aligned.m16n8k16.row.col.f32.bf16.bf16.f32 "
        "{%0,%1,%2,%3}, {%4,%5,%6,%7}, {%8,%9}, {%0,%1,%2,%3};"
        : "+f"(c[0]), "+f"(c[1]), "+f"(c[2]), "+f"(c[3])
        : "r"(a[0]), "r"(a[1]), "r"(a[2]), "r"(a[3]), "r"(b0), "r"(b1));
}

__device__ __forceinline__ void ldsm_x4(unsigned& r0, unsigned& r1, unsigned& r2, unsigned& r3,
                                        uint32_t addr) {
    asm volatile("ldmatrix.sync.aligned.m8n8.x4.shared.b16 {%0,%1,%2,%3}, [%4];"
                 : "=r"(r0), "=r"(r1), "=r"(r2), "=r"(r3) : "r"(addr));
}

// cp.async: .cg (L1-bypass) for h tiles — required for cross-SM coherence of ping-pong h.
__device__ __forceinline__ void cp_async16(uint32_t dst, const void* src) {
    asm volatile("cp.async.cg.shared.global [%0], [%1], 16;\n" :: "r"(dst), "l"(src));
}
__device__ __forceinline__ void cp_async4(uint32_t dst, const void* src) {
    asm volatile("cp.async.ca.shared.global [%0], [%1], 4;\n" :: "r"(dst), "l"(src));
}
__device__ __forceinline__ void cp_commit() { asm volatile("cp.async.commit_group;\n"); }
template <int N> __device__ __forceinline__ void cp_wait() {
    asm volatile("cp.async.wait_group %0;\n" :: "n"(N));
}

__global__ void init_kernel() {
    if (threadIdx.x < GRID) g_flags[threadIdx.x] = 0u;   // flags are monotonic within a launch
}

__global__ __launch_bounds__(NT)
void lstm_persistent_kernel(const float* __restrict__ strokes,
                            const float* __restrict__ W_ih,
                            const float* __restrict__ W_hh,
                            const float* __restrict__ b_ih,
                            const float* __restrict__ b_hh,
                            const float* __restrict__ W_out,
                            const float* __restrict__ b_out,
                            float* __restrict__ out) {
    extern __shared__ char smem[];
    __nv_bfloat16* sA    = (__nv_bfloat16*)smem;                           // [128][APITCH] h tile
    __nv_bfloat16* sBh   = (__nv_bfloat16*)(smem + SA_BYTES);              // [32][BP] W_hh hi
    __nv_bfloat16* sBl   = (__nv_bfloat16*)(smem + SA_BYTES + SBH_BYTES);  // [32][BP] W_hh lo
    float*         sx    = (float*)(smem + SA_BYTES + SBH_BYTES + SBL_BYTES);  // [128][5]
    float*         swih  = sx + 128 * INDIM;                               // [32][5]
    float*         sbias = swih + NC * INDIM;                              // [32]

    const int tid = threadIdx.x;
    const int q = blockIdx.x & 63;
    const int p = blockIdx.x >> 6;
    const int rowBase = p * 128;
    const int jBase = q * HC;

    // ---- One-time: W_hh slice -> bf16 hi/lo, W_ih slice, fused biases ----
    #pragma unroll
    for (int it = 0; it < 16; it++) {
        int idx = tid + it * NT;                        // 4096 float4 total (32 rows x 128)
        int n = idx >> 7, c = idx & 127;
        int gate = n >> 3, j = n & 7;
        const float4* src = (const float4*)(W_hh + (size_t)(gate * HID + jBase + j) * HID);
        float4 v = src[c];
        __nv_bfloat16 h0 = __float2bfloat16(v.x), h1 = __float2bfloat16(v.y);
        __nv_bfloat16 h2 = __float2bfloat16(v.z), h3 = __float2bfloat16(v.w);
        __nv_bfloat16* dh = sBh + n * BP + c * 4;
        __nv_bfloat16* dl = sBl + n * BP + c * 4;
        dh[0] = h0; dh[1] = h1; dh[2] = h2; dh[3] = h3;
        dl[0] = __float2bfloat16(v.x - __bfloat162float(h0));
        dl[1] = __float2bfloat16(v.y - __bfloat162float(h1));
        dl[2] = __float2bfloat16(v.z - __bfloat162float(h2));
        dl[3] = __float2bfloat16(v.w - __bfloat162float(h3));
    }
    if (tid < NC) {
        int gate = tid >> 3, j = tid & 7;
        int gr = gate * HID + jBase + j;
        sbias[tid] = b_ih[gr] + b_hh[gr];
        #pragma unroll
        for (int i = 0; i < INDIM; i++) swih[tid * INDIM + i] = W_ih[gr * INDIM + i];
    }
    __syncthreads();

    const uint32_t sa_base  = (uint32_t)__cvta_generic_to_shared(sA);
    const uint32_t sbh_base = (uint32_t)__cvta_generic_to_shared(sBh);
    const uint32_t sbl_base = (uint32_t)__cvta_generic_to_shared(sBl);
    const uint32_t sx_base  = (uint32_t)__cvta_generic_to_shared(sx);

    const int warp = tid >> 5, lane = tid & 31;
    const int g4 = lane >> 2, tg = lane & 3;
    const int band = warp * 16;                          // this warp's m16 band

    // ldmatrix lane-address bases (byte offsets into smem space)
    const int lg = lane >> 3, lr = lane & 7;
    // A tiles: T0=(m0-7,k0) T1=(m8-15,k0) T2=(m0-7,k8) T3=(m8-15,k8)
    const uint32_t aAddr0 = sa_base +
        (uint32_t)((band + (lg & 1) * 8 + lr) * APITCH + (lg >> 1) * 8) * 2;
    // B tiles: T0=(n0-7,k0) T1=(n0-7,k8) T2=(n8-15,k0) T3=(n8-15,k8)
    const uint32_t bOff = (uint32_t)(((lg >> 1) * 8 + lr) * BP + (lg & 1) * 8) * 2;
    const uint32_t bhAddr0 = sbh_base + bOff;            // n-tiles 0,1
    const uint32_t bhAddr1 = sbh_base + (uint32_t)(16 * BP * 2) + bOff;  // n-tiles 2,3
    const uint32_t blAddr0 = sbl_base + bOff;
    const uint32_t blAddr1 = sbl_base + (uint32_t)(16 * BP * 2) + bOff;

    // c state in registers: thread owns (row = band+g4+8*half, j = 2*tg+bb)
    float c_reg[2][2] = {{0.0f, 0.0f}, {0.0f, 0.0f}};

    for (int t = 0; t < SEQ; ++t) {
        const __nv_bfloat16* __restrict__ hin = g_h[t & 1] + rowBase * HID;
        __nv_bfloat16* __restrict__ hout = g_h[(t & 1) ^ 1];

        // ---- Issue x tile (group 0), then 4 A k-chunks (groups 1..4) ----
        for (int idx = tid; idx < 128 * INDIM; idx += NT) {
            int r = idx / INDIM, i = idx - r * INDIM;
            cp_async4(sx_base + (uint32_t)idx * 4,
                      strokes + (size_t)(rowBase + r) * (SEQ * INDIM) + t * INDIM + i);
        }
        cp_commit();
        if (t > 0) {
            const uint4* hin4 = (const uint4*)hin;       // [128 rows][64 uint4] (512 bf16/row)
            #pragma unroll
            for (int ch = 0; ch < 4; ch++) {
                // chunk ch = k-quarter: 128 rows x 16 uint4 = 2048 transfers -> 8 iters at NT=256
                #pragma unroll
                for (int it = 0; it < 8; it++) {
                    int idx = tid + it * NT;             // 0..2047
                    int r = idx >> 4;                    // 0..127
                    int cq = (idx & 15) + ch * 16;       // 0..63 (uint4 col within row)
                    cp_async16(sa_base + (uint32_t)(r * APITCH + cq * 8) * 2,
                               hin4 + r * 64 + cq);
                }
                cp_commit();
            }
            cp_wait<4>();                                // x landed
        } else {
            cp_wait<0>();
        }
        __syncthreads();

        // ---- x-projection into registers (hidden under A-chunk latency) ----
        float xs[2][2][4];
        #pragma unroll
        for (int half = 0; half < 2; half++) {
            const int rloc = band + g4 + half * 8;
            float xv[INDIM];
            #pragma unroll
            for (int i = 0; i < INDIM; i++) xv[i] = sx[rloc * INDIM + i];
            #pragma unroll
            for (int bb = 0; bb < 2; bb++) {
                const int j = 2 * tg + bb;
                #pragma unroll
                for (int gate = 0; gate < 4; gate++) {
                    const int n = gate * 8 + j;
                    float s = sbias[n];
                    #pragma unroll
                    for (int i = 0; i < INDIM; i++) s += xv[i] * swih[n * INDIM + i];
                    xs[half][bb][gate] = s;
                }
            }
        }

        float acc[4][4];
        #pragma unroll
        for (int a = 0; a < 4; a++)
            #pragma unroll
            for (int b = 0; b < 4; b++) acc[a][b] = 0.0f;

        if (t > 0) {
            // ---- MMA over 4 progressively-arriving k-chunks ----
            #pragma unroll
            for (int ch = 0; ch < 4; ch++) {
                switch (ch) {                             // wait_group needs an immediate
                    case 0: cp_wait<3>(); break;
                    case 1: cp_wait<2>(); break;
                    case 2: cp_wait<1>(); break;
                    default: cp_wait<0>(); break;
                }
                __syncthreads();
                #pragma unroll
                for (int i = 0; i < 8; i++) {
                    const uint32_t kb = (uint32_t)(ch * 128 + i * 16) * 2;  // byte offset
                    unsigned a[4], bh0[4], bh1[4], bl0[4], bl1[4];
                    ldsm_x4(a[0], a[1], a[2], a[3], aAddr0 + kb);
                    ldsm_x4(bh0[0], bh0[1], bh0[2], bh0[3], bhAddr0 + kb);
                    ldsm_x4(bh1[0], bh1[1], bh1[2], bh1[3], bhAddr1 + kb);
                    ldsm_x4(bl0[0], bl0[1], bl0[2], bl0[3], blAddr0 + kb);
                    ldsm_x4(bl1[0], bl1[1], bl1[2], bl1[3], blAddr1 + kb);
                    mma_bf16(acc[0], a, bh0[0], bh0[1]);
                    mma_bf16(acc[1], a, bh0[2], bh0[3]);
                    mma_bf16(acc[2], a, bh1[0], bh1[1]);
                    mma_bf16(acc[3], a, bh1[2], bh1[3]);
                    mma_bf16(acc[0], a, bl0[0], bl0[1]);
                    mma_bf16(acc[1], a, bl0[2], bl0[3]);
                    mma_bf16(acc[2], a, bl1[0], bl1[1]);
                    mma_bf16(acc[3], a, bl1[2], bl1[3]);
                }
            }
        }

        // ---- Epilogue: gates -> c/h update (c in regs), packed bf16x2 h store ----
        // C frag (m16n8): e0=(g4,2tg) e1=(g4,2tg+1) e2=(g4+8,2tg) e3=(g4+8,2tg+1)
        #pragma unroll
        for (int half = 0; half < 2; half++) {
            const int grow = rowBase + band + g4 + half * 8;
            __nv_bfloat16 hv[2];
            #pragma unroll
            for (int bb = 0; bb < 2; bb++) {
                const int e = half * 2 + bb;
                float iv = acc[0][e] + xs[half][bb][0];
                float fv = acc[1][e] + xs[half][bb][1];
                float gv = acc[2][e] + xs[half][bb][2];
                float ov = acc[3][e] + xs[half][bb][3];
                float cn = fast_sig(fv) * c_reg[half][bb] + fast_sig(iv) * fast_tanh(gv);
                c_reg[half][bb] = cn;
                hv[bb] = __float2bfloat16(fast_sig(ov) * fast_tanh(cn));
            }
            __nv_bfloat162 pack;
            pack.x = hv[0]; pack.y = hv[1];
            *(__nv_bfloat162*)(hout + (size_t)grow * HID + jBase + 2 * tg) = pack;
        }

        // ---- Distributed-flag grid barrier (128 CTAs co-resident: 1 CTA/SM) ----
        // Stores to 128 distinct addresses + parallel acquire-polls: no single-address
        // atomic convoy. st.release after __syncthreads orders this CTA's h stores
        // (happens-before is transitive through the CTA barrier).
        __syncthreads();
        if (tid == 0) {
            asm volatile("st.release.gpu.u32 [%0], %1;"
                         :: "l"(&g_flags[blockIdx.x]), "r"((unsigned)(t + 1)) : "memory");
        }
        if (tid < GRID) {
            const unsigned target = (unsigned)(t + 1);
            unsigned v;
            do {
                asm volatile("ld.acquire.gpu.u32 %0, [%1];"
                             : "=r"(v) : "l"(&g_flags[tid]) : "memory");
            } while (v < target);
        }
        __syncthreads();
    }

    // ---- Fused head: CTA bx -> batch rows 2bx, 2bx+1. Final h in g_h[0] (SEQ even). ----
    float* red = (float*)sx;
    {
        const int r = (blockIdx.x << 1) + (tid >> 7);
        const int cb = (tid & 127) * 4;
        const __nv_bfloat16* hp = g_h[0] + (size_t)r * HID + cb;
        uint2 v = __ldcg((const uint2*)hp);              // L1-bypass for coherence
        __nv_bfloat162 p0 = *reinterpret_cast<__nv_bfloat162*>(&v.x);
        __nv_bfloat162 p1 = *reinterpret_cast<__nv_bfloat162*>(&v.y);
        float s = __bfloat162float(p0.x) * W_out[cb]
                + __bfloat162float(p0.y) * W_out[cb + 1]
                + __bfloat162float(p1.x) * W_out[cb + 2]
                + __bfloat162float(p1.y) * W_out[cb + 3];
        #pragma unroll
        for (int o = 16; o; o >>= 1) s += __shfl_xor_sync(0xffffffffu, s, o);
        if (lane == 0) red[warp] = s;
    }
    __syncthreads();
    if (tid < 2) {
        float s = red[tid * 4] + red[tid * 4 + 1] + red[tid * 4 + 2] + red[tid * 4 + 3] + b_out[0];
        float lr = s > 0.0f ? s : 0.1f * s;
        out[(blockIdx.x << 1) + tid] = fast_sig(lr);
    }
}

extern "C" void kernel_launch(void* const* d_in, const int* in_sizes, int n_in,
                              void* d_out, int out_size) {
    const float* strokes = (const float*)d_in[0];
    const float* W_ih    = (const float*)d_in[1];
    const float* W_hh    = (const float*)d_in[2];
    const float* b_ih    = (const float*)d_in[3];
    const float* b_hh    = (const float*)d_in[4];
    const float* W_out   = (const float*)d_in[5];
    const float* b_out   = (const float*)d_in[6];
    float* out = (float*)d_out;

    cudaFuncSetAttribute(lstm_persistent_kernel,
                         cudaFuncAttributeMaxDynamicSharedMemorySize, SMEM_BYTES);

    init_kernel<<<1, GRID>>>();
    lstm_persistent_kernel<<<GRID, NT, SMEM_BYTES>>>(
        strokes, W_ih, W_hh, b_ih, b_hh, W_out, b_out, out);
}

// round 13
// speedup vs baseline: 1.7251x; 1.7251x over previous
#include <cuda_runtime.h>
#include <cuda_bf16.h>
#include <cstdint>

// Problem dims
#define BATCH 256
#define HID   512
#define SEQ   250
#define INDIM 5

// Persistent tiling: 128 CTAs = 2 batch groups (M=128) x 64 hidden slices (HC=8 -> N=32 gate cols)
#define GRID  128
#define NT    256          // 8 warps; each warp owns one m16 band, all 4 n8 tiles
#define HC 8
#define NC 32              // 4 gates * HC

// SMEM pitches (bf16 elements). 520*2B = 1040B, 1040 mod 128 = 16 -> ldmatrix conflict-free
#define APITCH 520
#define BP     520

#define SA_BYTES  (128 * APITCH * 2)           // 133120
#define SBH_BYTES (NC * BP * 2)                // 33280 (W_hh bf16)
#define SX_BYTES  (128 * INDIM * 4)            // 2560
#define SWIH_BYTES (NC * INDIM * 4)            // 640
#define SBIAS_BYTES (NC * 4)                   // 128
#define SMEM_BYTES (SA_BYTES + SBH_BYTES + SX_BYTES + SWIH_BYTES + SBIAS_BYTES) // 169728

// Persistent state (device globals: no allocation in kernel_launch)
__device__ __nv_bfloat16 g_h[2][BATCH * HID];
// Two independent p-group barriers; every counter/flag on its own 128B line.
__device__ unsigned g_sub[2][8][32];           // 8 sub-counters per group (8 CTAs each)
__device__ unsigned g_root[2][32];             // root counter per group
__device__ unsigned g_gen[2][32];              // generation flag per group (poll target)

__device__ __forceinline__ float fast_ex2(float x) {
    float y; asm("ex2.approx.f32 %0, %1;" : "=f"(y) : "f"(x)); return y;
}
__device__ __forceinline__ float fast_rcp(float x) {
    float y; asm("rcp.approx.f32 %0, %1;" : "=f"(y) : "f"(x)); return y;
}
__device__ __forceinline__ float fast_sig(float x) {
    return fast_rcp(1.0f + fast_ex2(-1.4426950408889634f * x));
}
__device__ __forceinline__ float fast_tanh(float x) {
    float s = fast_rcp(1.0f + fast_ex2(-2.8853900817779268f * x));
    return fmaf(2.0f, s, -1.0f);
}

__device__ __forceinline__ unsigned atom_add_acqrel(unsigned* p, unsigned v) {
    unsigned old;
    asm volatile("atom.add.acq_rel.gpu.u32 %0, [%1], %2;"
                 : "=r"(old) : "l"(p), "r"(v) : "memory");
    return old;
}

__device__ __forceinline__ void mma_bf16(float* c, const unsigned* a, unsigned b0, unsigned b1) {
    asm volatile(
        "mma.sync.aligned.m16n8k16.row.col.f32.bf16.bf16.f32 "
        "{%0,%1,%2,%3}, {%4,%5,%6,%7}, {%8,%9}, {%0,%1,%2,%3};"
        : "+f"(c[0]), "+f"(c[1]), "+f"(c[2]), "+f"(c[3])
        : "r"(a[0]), "r"(a[1]), "r"(a[2]), "r"(a[3]), "r"(b0), "r"(b1));
}

__device__ __forceinline__ void ldsm_x4(unsigned& r0, unsigned& r1, unsigned& r2, unsigned& r3,
                                        uint32_t addr) {
    asm volatile("ldmatrix.sync.aligned.m8n8.x4.shared.b16 {%0,%1,%2,%3}, [%4];"
                 : "=r"(r0), "=r"(r1), "=r"(r2), "=r"(r3) : "r"(addr));
}

// cp.async: .cg (L1-bypass) for h tiles — required for cross-SM coherence of ping-pong h.
__device__ __forceinline__ void cp_async16(uint32_t dst, const void* src) {
    asm volatile("cp.async.cg.shared.global [%0], [%1], 16;\n" :: "r"(dst), "l"(src));
}
__device__ __forceinline__ void cp_async4(uint32_t dst, const void* src) {
    asm volatile("cp.async.ca.shared.global [%0], [%1], 4;\n" :: "r"(dst), "l"(src));
}
__device__ __forceinline__ void cp_commit() { asm volatile("cp.async.commit_group;\n"); }
template <int N> __device__ __forceinline__ void cp_wait() {
    asm volatile("cp.async.wait_group %0;\n" :: "n"(N));
}

__global__ void init_kernel() {
    // Reset all barrier state each launch (counters are monotonic within a launch).
    unsigned* base = &g_sub[0][0][0];
    int total = 2 * 8 * 32 + 2 * 32 + 2 * 32;            // g_sub, g_root, g_gen contiguous? no —
    (void)total;                                          // zero each array explicitly instead
    for (int i = threadIdx.x; i < 2 * 8 * 32; i += blockDim.x) base[i] = 0u;
    for (int i = threadIdx.x; i < 2 * 32; i += blockDim.x) (&g_root[0][0])[i] = 0u;
    for (int i = threadIdx.x; i < 2 * 32; i += blockDim.x) (&g_gen[0][0])[i] = 0u;
}

__global__ __launch_bounds__(NT)
void lstm_persistent_kernel(const float* __restrict__ strokes,
                            const float* __restrict__ W_ih,
                            const float* __restrict__ W_hh,
                            const float* __restrict__ b_ih,
                            const float* __restrict__ b_hh,
                            const float* __restrict__ W_out,
                            const float* __restrict__ b_out,
                            float* __restrict__ out) {
    extern __shared__ char smem[];
    __nv_bfloat16* sA    = (__nv_bfloat16*)smem;                           // [128][APITCH] h tile
    __nv_bfloat16* sBh   = (__nv_bfloat16*)(smem + SA_BYTES);              // [32][BP] W_hh bf16
    float*         sx    = (float*)(smem + SA_BYTES + SBH_BYTES);          // [128][5]
    float*         swih  = sx + 128 * INDIM;                               // [32][5]
    float*         sbias = swih + NC * INDIM;                              // [32]

    const int tid = threadIdx.x;
    const int q = blockIdx.x & 63;
    const int p = blockIdx.x >> 6;
    const int rowBase = p * 128;
    const int jBase = q * HC;

    // ---- One-time: W_hh slice -> bf16, W_ih slice, fused biases ----
    #pragma unroll
    for (int it = 0; it < 16; it++) {
        int idx = tid + it * NT;                        // 4096 float4 total (32 rows x 128)
        int n = idx >> 7, c = idx & 127;
        int gate = n >> 3, j = n & 7;
        const float4* src = (const float4*)(W_hh + (size_t)(gate * HID + jBase + j) * HID);
        float4 v = src[c];
        __nv_bfloat16* dh = sBh + n * BP + c * 4;
        dh[0] = __float2bfloat16(v.x); dh[1] = __float2bfloat16(v.y);
        dh[2] = __float2bfloat16(v.z); dh[3] = __float2bfloat16(v.w);
    }
    if (tid < NC) {
        int gate = tid >> 3, j = tid & 7;
        int gr = gate * HID + jBase + j;
        sbias[tid] = b_ih[gr] + b_hh[gr];
        #pragma unroll
        for (int i = 0; i < INDIM; i++) swih[tid * INDIM + i] = W_ih[gr * INDIM + i];
    }
    __syncthreads();

    const uint32_t sa_base  = (uint32_t)__cvta_generic_to_shared(sA);
    const uint32_t sbh_base = (uint32_t)__cvta_generic_to_shared(sBh);
    const uint32_t sx_base  = (uint32_t)__cvta_generic_to_shared(sx);

    const int warp = tid >> 5, lane = tid & 31;
    const int g4 = lane >> 2, tg = lane & 3;
    const int band = warp * 16;                          // this warp's m16 band

    // ldmatrix lane-address bases (byte offsets into smem space)
    const int lg = lane >> 3, lr = lane & 7;
    // A tiles: T0=(m0-7,k0) T1=(m8-15,k0) T2=(m0-7,k8) T3=(m8-15,k8)
    const uint32_t aAddr0 = sa_base +
        (uint32_t)((band + (lg & 1) * 8 + lr) * APITCH + (lg >> 1) * 8) * 2;
    // B tiles: T0=(n0-7,k0) T1=(n0-7,k8) T2=(n8-15,k0) T3=(n8-15,k8)
    const uint32_t bOff = (uint32_t)(((lg >> 1) * 8 + lr) * BP + (lg & 1) * 8) * 2;
    const uint32_t bhAddr0 = sbh_base + bOff;            // n-tiles 0,1
    const uint32_t bhAddr1 = sbh_base + (uint32_t)(16 * BP * 2) + bOff;  // n-tiles 2,3

    // c state in registers: thread owns (row = band+g4+8*half, j = 2*tg+bb)
    float c_reg[2][2] = {{0.0f, 0.0f}, {0.0f, 0.0f}};

    // ---- Prefetch x for t=0 (group 0) ----
    for (int idx = tid; idx < 128 * INDIM; idx += NT) {
        int r = idx / INDIM, i = idx - r * INDIM;
        cp_async4(sx_base + (uint32_t)idx * 4,
                  strokes + (size_t)(rowBase + r) * (SEQ * INDIM) + 0 * INDIM + i);
    }
    cp_commit();

    for (int t = 0; t < SEQ; ++t) {
        const __nv_bfloat16* __restrict__ hin = g_h[t & 1] + rowBase * HID;
        __nv_bfloat16* __restrict__ hout = g_h[(t & 1) ^ 1];

        // ---- Issue 4 A k-chunks (x for this step was prefetched last iteration) ----
        if (t > 0) {
            const uint4* hin4 = (const uint4*)hin;       // [128 rows][64 uint4] (512 bf16/row)
            #pragma unroll
            for (int ch = 0; ch < 4; ch++) {
                // chunk ch = k-quarter: 128 rows x 16 uint4 = 2048 transfers -> 8 iters at NT=256
                #pragma unroll
                for (int it = 0; it < 8; it++) {
                    int idx = tid + it * NT;             // 0..2047
                    int r = idx >> 4;                    // 0..127
                    int cq = (idx & 15) + ch * 16;       // 0..63 (uint4 col within row)
                    cp_async16(sa_base + (uint32_t)(r * APITCH + cq * 8) * 2,
                               hin4 + r * 64 + cq);
                }
                cp_commit();
            }
            cp_wait<4>();                                // x landed (oldest group)
        } else {
            cp_wait<0>();
        }
        __syncthreads();

        // ---- x-projection into registers (hidden under A-chunk latency) ----
        float xs[2][2][4];
        #pragma unroll
        for (int half = 0; half < 2; half++) {
            const int rloc = band + g4 + half * 8;
            float xv[INDIM];
            #pragma unroll
            for (int i = 0; i < INDIM; i++) xv[i] = sx[rloc * INDIM + i];
            #pragma unroll
            for (int bb = 0; bb < 2; bb++) {
                const int j = 2 * tg + bb;
                #pragma unroll
                for (int gate = 0; gate < 4; gate++) {
                    const int n = gate * 8 + j;
                    float s = sbias[n];
                    #pragma unroll
                    for (int i = 0; i < INDIM; i++) s += xv[i] * swih[n * INDIM + i];
                    xs[half][bb][gate] = s;
                }
            }
        }

        float acc[4][4];
        #pragma unroll
        for (int a = 0; a < 4; a++)
            #pragma unroll
            for (int b = 0; b < 4; b++) acc[a][b] = 0.0f;

        if (t > 0) {
            // ---- MMA over 4 progressively-arriving k-chunks (hi-only bf16 W) ----
            #pragma unroll
            for (int ch = 0; ch < 4; ch++) {
                switch (ch) {                             // wait_group needs an immediate
                    case 0: cp_wait<3>(); break;
                    case 1: cp_wait<2>(); break;
                    case 2: cp_wait<1>(); break;
                    default: cp_wait<0>(); break;
                }
                __syncthreads();
                #pragma unroll
                for (int i = 0; i < 8; i++) {
                    const uint32_t kb = (uint32_t)(ch * 128 + i * 16) * 2;  // byte offset
                    unsigned a[4], bh0[4], bh1[4];
                    ldsm_x4(a[0], a[1], a[2], a[3], aAddr0 + kb);
                    ldsm_x4(bh0[0], bh0[1], bh0[2], bh0[3], bhAddr0 + kb);
                    ldsm_x4(bh1[0], bh1[1], bh1[2], bh1[3], bhAddr1 + kb);
                    mma_bf16(acc[0], a, bh0[0], bh0[1]);
                    mma_bf16(acc[1], a, bh0[2], bh0[3]);
                    mma_bf16(acc[2], a, bh1[0], bh1[1]);
                    mma_bf16(acc[3], a, bh1[2], bh1[3]);
                }
            }
        }

        // ---- Epilogue: gates -> c/h update (c in regs), packed bf16x2 h store ----
        // C frag (m16n8): e0=(g4,2tg) e1=(g4,2tg+1) e2=(g4+8,2tg) e3=(g4+8,2tg+1)
        #pragma unroll
        for (int half = 0; half < 2; half++) {
            const int grow = rowBase + band + g4 + half * 8;
            __nv_bfloat16 hv[2];
            #pragma unroll
            for (int bb = 0; bb < 2; bb++) {
                const int e = half * 2 + bb;
                float iv = acc[0][e] + xs[half][bb][0];
                float fv = acc[1][e] + xs[half][bb][1];
                float gv = acc[2][e] + xs[half][bb][2];
                float ov = acc[3][e] + xs[half][bb][3];
                float cn = fast_sig(fv) * c_reg[half][bb] + fast_sig(iv) * fast_tanh(gv);
                c_reg[half][bb] = cn;
                hv[bb] = __float2bfloat16(fast_sig(ov) * fast_tanh(cn));
            }
            __nv_bfloat162 pack;
            pack.x = hv[0]; pack.y = hv[1];
            *(__nv_bfloat162*)(hout + (size_t)grow * HID + jBase + 2 * tg) = pack;
        }

        __syncthreads();                                 // h stores + sx reads complete CTA-wide

        // ---- Prefetch x for t+1 (rides out the barrier wait) ----
        if (t + 1 < SEQ) {
            for (int idx = tid; idx < 128 * INDIM; idx += NT) {
                int r = idx / INDIM, i = idx - r * INDIM;
                cp_async4(sx_base + (uint32_t)idx * 4,
                          strokes + (size_t)(rowBase + r) * (SEQ * INDIM) + (t + 1) * INDIM + i);
            }
            cp_commit();
        }

        // ---- Two-level p-group barrier (64 CTAs; batch halves are independent).
        //      Arrivals: acq_rel atomics on line-isolated counters (8 sub + 1 root).
        //      Wait: ONE thread polls the line-isolated gen flag (no poll storm). ----
        if (tid == 0) {
            unsigned a = atom_add_acqrel(&g_sub[p][q >> 3][0], 1u);
            if ((a & 7u) == 7u) {                        // 8th arrival in sub-group this step
                unsigned r = atom_add_acqrel(&g_root[p][0], 1u);
                if ((r & 7u) == 7u) {                    // 8th sub-group: release the step
                    asm volatile("st.release.gpu.u32 [%0], %1;"
                                 :: "l"(&g_gen[p][0]), "r"((unsigned)(t + 1)) : "memory");
                }
            }
            const unsigned target = (unsigned)(t + 1);
            unsigned v;
            do {
                asm volatile("ld.acquire.gpu.u32 %0, [%1];"
                             : "=r"(v) : "l"(&g_gen[p][0]) : "memory");
            } while (v < target);
        }
        __syncthreads();
    }

    // ---- Fused head: CTA bx -> batch rows 2bx, 2bx+1 (stays within this p-group).
    //      Final h in g_h[0] (SEQ even). ----
    float* red = (float*)sx;
    {
        const int r = (blockIdx.x << 1) + (tid >> 7);
        const int cb = (tid & 127) * 4;
        const __nv_bfloat16* hp = g_h[0] + (size_t)r * HID + cb;
        uint2 v = __ldcg((const uint2*)hp);              // L1-bypass for coherence
        __nv_bfloat162 p0 = *reinterpret_cast<__nv_bfloat162*>(&v.x);
        __nv_bfloat162 p1 = *reinterpret_cast<__nv_bfloat162*>(&v.y);
        float s = __bfloat162float(p0.x) * W_out[cb]
                + __bfloat162float(p0.y) * W_out[cb + 1]
                + __bfloat162float(p1.x) * W_out[cb + 2]
                + __bfloat162float(p1.y) * W_out[cb + 3];
        #pragma unroll
        for (int o = 16; o; o >>= 1) s += __shfl_xor_sync(0xffffffffu, s, o);
        if (lane == 0) red[warp] = s;
    }
    __syncthreads();
    if (tid < 2) {
        float s = red[tid * 4] + red[tid * 4 + 1] + red[tid * 4 + 2] + red[tid * 4 + 3] + b_out[0];
        float lr = s > 0.0f ? s : 0.1f * s;
        out[(blockIdx.x << 1) + tid] = fast_sig(lr);
    }
}

extern "C" void kernel_launch(void* const* d_in, const int* in_sizes, int n_in,
                              void* d_out, int out_size) {
    const float* strokes = (const float*)d_in[0];
    const float* W_ih    = (const float*)d_in[1];
    const float* W_hh    = (const float*)d_in[2];
    const float* b_ih    = (const float*)d_in[3];
    const float* b_hh    = (const float*)d_in[4];
    const float* W_out   = (const float*)d_in[5];
    const float* b_out   = (const float*)d_in[6];
    float* out = (float*)d_out;

    cudaFuncSetAttribute(lstm_persistent_kernel,
                         cudaFuncAttributeMaxDynamicSharedMemorySize, SMEM_BYTES);

    init_kernel<<<1, 256>>>();
    lstm_persistent_kernel<<<GRID, NT, SMEM_BYTES>>>(
        strokes, W_ih, W_hh, b_ih, b_hh, W_out, b_out, out);
}

// round 14
// speedup vs baseline: 1.9619x; 1.1373x over previous
#include <cuda_runtime.h>
#include <cuda.h>
#include <cuda_bf16.h>
#include <cstdint>

// Problem dims
#define BATCH 256
#define HID   512
#define SEQ   250
#define INDIM 5

// Persistent tiling: 128 CTAs = 2 batch groups (M=128) x 64 hidden slices (HC=8 -> N=32 gate cols)
#define GRID  128
#define NT    256          // 8 warps; each warp owns one m16 band, all 4 n8 tiles
#define HC 8
#define NC 32              // 4 gates * HC

#define BP 520             // W tile pitch (bf16); 1040B rows -> conflict-free ldmatrix

// A tile: 8 regions of [128 rows x 128 B], TMA SW128-swizzled. 131072 B total.
#define SA_BYTES   131072
#define OFF_SBH    SA_BYTES
#define SBH_BYTES  (NC * BP * 2)                 // 33280
#define OFF_SWIH   (OFF_SBH + SBH_BYTES)
#define OFF_SBIAS  (OFF_SWIH + NC * INDIM * 4)
#define OFF_MBAR   (OFF_SBIAS + NC * 4)          // 4 mbarriers, 8B each
#define OFF_RED    (OFF_MBAR + 64)
#define SMEM_BYTES (OFF_RED + 64 + 1024)         // +1024 slack for in-kernel 1KB alignment

// Persistent state (device globals: no allocation in kernel_launch)
__device__ __nv_bfloat16 g_h[2][BATCH * HID];
// Two independent p-group barriers; every counter/flag on its own 128B line.
__device__ unsigned g_sub[2][8][32];
__device__ unsigned g_root[2][32];
__device__ unsigned g_gen[2][32];

__device__ __forceinline__ float fast_ex2(float x) {
    float y; asm("ex2.approx.f32 %0, %1;" : "=f"(y) : "f"(x)); return y;
}
__device__ __forceinline__ float fast_rcp(float x) {
    float y; asm("rcp.approx.f32 %0, %1;" : "=f"(y) : "f"(x)); return y;
}
__device__ __forceinline__ float fast_sig(float x) {
    return fast_rcp(1.0f + fast_ex2(-1.4426950408889634f * x));
}
__device__ __forceinline__ float fast_tanh(float x) {
    float s = fast_rcp(1.0f + fast_ex2(-2.8853900817779268f * x));
    return fmaf(2.0f, s, -1.0f);
}

__device__ __forceinline__ unsigned atom_add_acqrel(unsigned* p, unsigned v) {
    unsigned old;
    asm volatile("atom.add.acq_rel.gpu.u32 %0, [%1], %2;"
                 : "=r"(old) : "l"(p), "r"(v) : "memory");
    return old;
}

__device__ __forceinline__ void mma_bf16(float* c, const unsigned* a, unsigned b0, unsigned b1) {
    asm volatile(
        "mma.sync.aligned.m16n8k16.row.col.f32.bf16.bf16.f32 "
        "{%0,%1,%2,%3}, {%4,%5,%6,%7}, {%8,%9}, {%0,%1,%2,%3};"
        : "+f"(c[0]), "+f"(c[1]), "+f"(c[2]), "+f"(c[3])
        : "r"(a[0]), "r"(a[1]), "r"(a[2]), "r"(a[3]), "r"(b0), "r"(b1));
}

__device__ __forceinline__ void ldsm_x4(unsigned& r0, unsigned& r1, unsigned& r2, unsigned& r3,
                                        uint32_t addr) {
    asm volatile("ldmatrix.sync.aligned.m8n8.x4.shared.b16 {%0,%1,%2,%3}, [%4];"
                 : "=r"(r0), "=r"(r1), "=r"(r2), "=r"(r3) : "r"(addr));
}

// Warp-converged mbarrier parity wait (HW sleep, no CTA sync needed).
__device__ __forceinline__ void mbar_wait(uint32_t mbar, unsigned parity) {
    asm volatile(
        "{\n\t.reg .pred p;\n\t"
        "WAIT_%=:\n\t"
        "mbarrier.try_wait.parity.acquire.cta.shared::cta.b64 p, [%0], %1, 0x989680;\n\t"
        "@p bra.uni DONE_%=;\n\t"
        "bra.uni WAIT_%=;\n\t"
        "DONE_%=:\n\t}"
        :: "r"(mbar), "r"(parity) : "memory");
}

__global__ void init_kernel() {
    unsigned* base = &g_sub[0][0][0];
    for (int i = threadIdx.x; i < 2 * 8 * 32; i += blockDim.x) base[i] = 0u;
    for (int i = threadIdx.x; i < 2 * 32; i += blockDim.x) (&g_root[0][0])[i] = 0u;
    for (int i = threadIdx.x; i < 2 * 32; i += blockDim.x) (&g_gen[0][0])[i] = 0u;
}

__global__ __launch_bounds__(NT)
void lstm_persistent_kernel(const float* __restrict__ strokes,
                            const float* __restrict__ W_ih,
                            const float* __restrict__ W_hh,
                            const float* __restrict__ b_ih,
                            const float* __restrict__ b_hh,
                            const float* __restrict__ W_out,
                            const float* __restrict__ b_out,
                            float* __restrict__ out,
                            const __grid_constant__ CUtensorMap tmapA,   // g_h[0]
                            const __grid_constant__ CUtensorMap tmapB) { // g_h[1]
    extern __shared__ char smem_raw[];
    // Align the A tile to 1KB so the SW128 swizzle pattern matches TMA's (abs-addr bits).
    uint32_t raw = (uint32_t)__cvta_generic_to_shared(smem_raw);
    const uint32_t sa_base = (raw + 1023u) & ~1023u;
    char* base_ptr = smem_raw + (sa_base - raw);

    __nv_bfloat16* sBh   = (__nv_bfloat16*)(base_ptr + OFF_SBH);
    float*         swih  = (float*)(base_ptr + OFF_SWIH);
    float*         sbias = (float*)(base_ptr + OFF_SBIAS);
    const uint32_t mb_base = sa_base + OFF_MBAR;
    const uint32_t sbh_base = sa_base + OFF_SBH;

    const int tid = threadIdx.x;
    const int q = blockIdx.x & 63;
    const int p = blockIdx.x >> 6;
    const int rowBase = p * 128;
    const int jBase = q * HC;

    // ---- One-time: W_hh slice -> bf16, W_ih slice, fused biases, mbarrier init ----
    #pragma unroll
    for (int it = 0; it < 16; it++) {
        int idx = tid + it * NT;                        // 4096 float4 (32 rows x 128)
        int n = idx >> 7, c = idx & 127;
        int gate = n >> 3, j = n & 7;
        const float4* src = (const float4*)(W_hh + (size_t)(gate * HID + jBase + j) * HID);
        float4 v = src[c];
        __nv_bfloat16* dh = sBh + n * BP + c * 4;
        dh[0] = __float2bfloat16(v.x); dh[1] = __float2bfloat16(v.y);
        dh[2] = __float2bfloat16(v.z); dh[3] = __float2bfloat16(v.w);
    }
    if (tid < NC) {
        int gate = tid >> 3, j = tid & 7;
        int gr = gate * HID + jBase + j;
        sbias[tid] = b_ih[gr] + b_hh[gr];
        #pragma unroll
        for (int i = 0; i < INDIM; i++) swih[tid * INDIM + i] = W_ih[gr * INDIM + i];
    }
    if (tid == 0) {
        #pragma unroll
        for (int s = 0; s < 4; s++)
            asm volatile("mbarrier.init.shared.b64 [%0], %1;"
                         :: "r"(mb_base + s * 8), "r"(1u) : "memory");
    }
    __syncthreads();

    const int warp = tid >> 5, lane = tid & 31;
    const int g4 = lane >> 2, tg = lane & 3;
    const int band = warp * 16;

    // ---- A-fragment addressing in the TMA SW128 layout.
    // Region r (64 cols) at sa_base + r*16384; elem (row, col) at
    // row*128 + ((col&63)*2 ^ ((row&7)*16)) within the region.
    const int lg = lane >> 3, lr = lane & 7;
    const int arow = band + (lg & 1) * 8 + lr;           // lane's A row (within warp band)
    const uint32_t aLaneBase = sa_base + (uint32_t)arow * 128u;
    const uint32_t aXor = (uint32_t)((arow & 7) * 16);
    const uint32_t aKlg = (uint32_t)((lg >> 1) * 16);    // k-half byte offset (0 or 16)

    // B tiles unchanged (padded pitch layout): T0=(n0-7,k0) T1=(n0-7,k8) T2=(n8-15,k0) T3=(n8-15,k8)
    const uint32_t bOff = (uint32_t)(((lg >> 1) * 8 + lr) * BP + (lg & 1) * 8) * 2;
    const uint32_t bhAddr0 = sbh_base + bOff;
    const uint32_t bhAddr1 = sbh_base + (uint32_t)(16 * BP * 2) + bOff;

    // c state in registers; x rows in registers (strokes immutable -> plain LDG is safe)
    float c_reg[2][2] = {{0.0f, 0.0f}, {0.0f, 0.0f}};
    const float* xPtr0 = strokes + (size_t)(rowBase + band + g4) * (SEQ * INDIM);
    const float* xPtr1 = xPtr0 + (size_t)8 * (SEQ * INDIM);
    float xv0[INDIM], xv1[INDIM];
    #pragma unroll
    for (int i = 0; i < INDIM; i++) { xv0[i] = xPtr0[i]; xv1[i] = xPtr1[i]; }   // t=0

    for (int t = 0; t < SEQ; ++t) {
        // ---- x-projection from registers (while TMA chunks stream in) ----
        float xs[2][2][4];
        #pragma unroll
        for (int half = 0; half < 2; half++) {
            const float* xv = half ? xv1 : xv0;
            #pragma unroll
            for (int bb = 0; bb < 2; bb++) {
                const int j = 2 * tg + bb;
                #pragma unroll
                for (int gate = 0; gate < 4; gate++) {
                    const int n = gate * 8 + j;
                    float s = sbias[n];
                    #pragma unroll
                    for (int i = 0; i < INDIM; i++) s += xv[i] * swih[n * INDIM + i];
                    xs[half][bb][gate] = s;
                }
            }
        }
        // ---- Prefetch x for t+1 (consumed next iteration; latency fully hidden) ----
        if (t + 1 < SEQ) {
            const float* n0 = xPtr0 + (t + 1) * INDIM;
            const float* n1 = xPtr1 + (t + 1) * INDIM;
            #pragma unroll
            for (int i = 0; i < INDIM; i++) { xv0[i] = n0[i]; xv1[i] = n1[i]; }
        }

        float acc[4][4];
        #pragma unroll
        for (int a = 0; a < 4; a++)
            #pragma unroll
            for (int b = 0; b < 4; b++) acc[a][b] = 0.0f;

        if (t > 0) {
            // ---- MMA over 4 TMA chunks; warp-local mbarrier waits, no CTA syncs ----
            const unsigned par = (unsigned)((t - 1) & 1);
            #pragma unroll
            for (int ch = 0; ch < 4; ch++) {
                mbar_wait(mb_base + ch * 8, par);
                #pragma unroll
                for (int i = 0; i < 8; i++) {
                    const int k0 = ch * 128 + i * 16;
                    const uint32_t aAddr = aLaneBase + (uint32_t)(k0 >> 6) * 16384u
                                         + (((uint32_t)((k0 & 63) * 2) | aKlg) ^ aXor);
                    const uint32_t kb = (uint32_t)(k0 * 2);
                    unsigned a[4], bh0[4], bh1[4];
                    ldsm_x4(a[0], a[1], a[2], a[3], aAddr);
                    ldsm_x4(bh0[0], bh0[1], bh0[2], bh0[3], bhAddr0 + kb);
                    ldsm_x4(bh1[0], bh1[1], bh1[2], bh1[3], bhAddr1 + kb);
                    mma_bf16(acc[0], a, bh0[0], bh0[1]);
                    mma_bf16(acc[1], a, bh0[2], bh0[3]);
                    mma_bf16(acc[2], a, bh1[0], bh1[1]);
                    mma_bf16(acc[3], a, bh1[2], bh1[3]);
                }
            }
        }

        // ---- Epilogue: gates -> c/h update (c in regs), packed bf16x2 h store ----
        __nv_bfloat16* __restrict__ hout = g_h[(t & 1) ^ 1];
        #pragma unroll
        for (int half = 0; half < 2; half++) {
            const int grow = rowBase + band + g4 + half * 8;
            __nv_bfloat16 hv[2];
            #pragma unroll
            for (int bb = 0; bb < 2; bb++) {
                const int e = half * 2 + bb;
                float iv = acc[0][e] + xs[half][bb][0];
                float fv = acc[1][e] + xs[half][bb][1];
                float gv = acc[2][e] + xs[half][bb][2];
                float ov = acc[3][e] + xs[half][bb][3];
                float cn = fast_sig(fv) * c_reg[half][bb] + fast_sig(iv) * fast_tanh(gv);
                c_reg[half][bb] = cn;
                hv[bb] = __float2bfloat16(fast_sig(ov) * fast_tanh(cn));
            }
            __nv_bfloat162 pack;
            pack.x = hv[0]; pack.y = hv[1];
            *(__nv_bfloat162*)(hout + (size_t)grow * HID + jBase + 2 * tg) = pack;
        }

        // This syncthreads both (a) makes all warps' h stores precede the arrival and
        // (b) guarantees all smem A reads of step t are done before TMA t+1 overwrites sA.
        __syncthreads();

        // ---- tid0: two-level barrier arrive + poll, then issue next step's TMA.
        //      Other warps sleep directly on the mbarriers (the mbar IS the release). ----
        if (tid == 0) {
            unsigned a = atom_add_acqrel(&g_sub[p][q >> 3][0], 1u);
            if ((a & 7u) == 7u) {
                unsigned r = atom_add_acqrel(&g_root[p][0], 1u);
                if ((r & 7u) == 7u) {
                    asm volatile("st.release.gpu.u32 [%0], %1;"
                                 :: "l"(&g_gen[p][0]), "r"((unsigned)(t + 1)) : "memory");
                }
            }
            const unsigned target = (unsigned)(t + 1);
            unsigned v;
            do {
                asm volatile("ld.acquire.gpu.u32 %0, [%1];"
                             : "=r"(v) : "l"(&g_gen[p][0]) : "memory");
            } while (v < target);
            asm volatile("fence.proxy.async;" ::: "memory");   // order acquire before TMA reads
            if (t + 1 < SEQ) {
                const void* mp = ((t + 1) & 1) ? (const void*)&tmapB : (const void*)&tmapA;
                #pragma unroll
                for (int ch = 0; ch < 4; ch++) {
                    const uint32_t mb = mb_base + ch * 8;
                    asm volatile("mbarrier.arrive.expect_tx.shared.b64 _, [%0], %1;"
                                 :: "r"(mb), "r"(32768u) : "memory");
                    asm volatile(
                        "cp.async.bulk.tensor.2d.shared::cta.global.tile.mbarrier::complete_tx::bytes "
                        "[%0], [%1, {%2, %3}], [%4];"
                        :: "r"(sa_base + (uint32_t)(2 * ch) * 16384u), "l"(mp),
                           "r"(ch * 256), "r"(rowBase), "r"(mb) : "memory");
                    asm volatile(
                        "cp.async.bulk.tensor.2d.shared::cta.global.tile.mbarrier::complete_tx::bytes "
                        "[%0], [%1, {%2, %3}], [%4];"
                        :: "r"(sa_base + (uint32_t)(2 * ch + 1) * 16384u), "l"(mp),
                           "r"(ch * 256 + 128), "r"(rowBase), "r"(mb) : "memory");
                }
            }
        }
        if (warp == 0) __syncwarp();                    // reconverge warp 0 before ldmatrix
    }

    __syncthreads();                                    // all CTAs arrived (tid0 polled gen==SEQ)

    // ---- Fused head: CTA bx -> batch rows 2bx, 2bx+1. Final h in g_h[0] (SEQ even). ----
    float* red = (float*)(base_ptr + OFF_RED);
    {
        const int r = (blockIdx.x << 1) + (tid >> 7);
        const int cb = (tid & 127) * 4;
        const __nv_bfloat16* hp = g_h[0] + (size_t)r * HID + cb;
        uint2 v = __ldcg((const uint2*)hp);             // L1-bypass for coherence
        __nv_bfloat162 p0 = *reinterpret_cast<__nv_bfloat162*>(&v.x);
        __nv_bfloat162 p1 = *reinterpret_cast<__nv_bfloat162*>(&v.y);
        float s = __bfloat162float(p0.x) * W_out[cb]
                + __bfloat162float(p0.y) * W_out[cb + 1]
                + __bfloat162float(p1.x) * W_out[cb + 2]
                + __bfloat162float(p1.y) * W_out[cb + 3];
        #pragma unroll
        for (int o = 16; o; o >>= 1) s += __shfl_xor_sync(0xffffffffu, s, o);
        if (lane == 0) red[warp] = s;
    }
    __syncthreads();
    if (tid < 2) {
        float s = red[tid * 4] + red[tid * 4 + 1] + red[tid * 4 + 2] + red[tid * 4 + 3] + b_out[0];
        float lr = s > 0.0f ? s : 0.1f * s;
        out[(blockIdx.x << 1) + tid] = fast_sig(lr);
    }
}

typedef CUresult (CUDAAPI *PFN_encodeTiled_t)(
    CUtensorMap*, CUtensorMapDataType, cuuint32_t, void*,
    const cuuint64_t*, const cuuint64_t*, const cuuint32_t*, const cuuint32_t*,
    CUtensorMapInterleave, CUtensorMapSwizzle, CUtensorMapL2promotion, CUtensorMapFloatOOBfill);

extern "C" void kernel_launch(void* const* d_in, const int* in_sizes, int n_in,
                              void* d_out, int out_size) {
    const float* strokes = (const float*)d_in[0];
    const float* W_ih    = (const float*)d_in[1];
    const float* W_hh    = (const float*)d_in[2];
    const float* b_ih    = (const float*)d_in[3];
    const float* b_hh    = (const float*)d_in[4];
    const float* W_out   = (const float*)d_in[5];
    const float* b_out   = (const float*)d_in[6];
    float* out = (float*)d_out;

    // Build TMA maps for the two h ping-pong buffers (host-side, no stream ops:
    // legal during graph capture; no allocation).
    PFN_encodeTiled_t pfn = nullptr;
    cudaDriverEntryPointQueryResult st;
#if CUDART_VERSION >= 12050
    cudaGetDriverEntryPointByVersion("cuTensorMapEncodeTiled", (void**)&pfn, 12000,
                                     cudaEnableDefault, &st);
#else
    cudaGetDriverEntryPoint("cuTensorMapEncodeTiled", (void**)&pfn, cudaEnableDefault, &st);
#endif
    void* ghp = nullptr;
    cudaGetSymbolAddress(&ghp, g_h);

    CUtensorMap tmA, tmB;
    cuuint64_t gd[2] = {1024ull, 256ull};     // bytes per row, rows (uint8 view)
    cuuint64_t gs[1] = {1024ull};             // row stride in bytes
    cuuint32_t bx[2] = {128u, 128u};          // 128B x 128-row box (SW128 limit)
    cuuint32_t es[2] = {1u, 1u};
    pfn(&tmA, CU_TENSOR_MAP_DATA_TYPE_UINT8, 2, ghp, gd, gs, bx, es,
        CU_TENSOR_MAP_INTERLEAVE_NONE, CU_TENSOR_MAP_SWIZZLE_128B,
        CU_TENSOR_MAP_L2_PROMOTION_L2_128B, CU_TENSOR_MAP_FLOAT_OOB_FILL_NONE);
    pfn(&tmB, CU_TENSOR_MAP_DATA_TYPE_UINT8, 2, (void*)((char*)ghp + (size_t)BATCH * HID * 2),
        gd, gs, bx, es,
        CU_TENSOR_MAP_INTERLEAVE_NONE, CU_TENSOR_MAP_SWIZZLE_128B,
        CU_TENSOR_MAP_L2_PROMOTION_L2_128B, CU_TENSOR_MAP_FLOAT_OOB_FILL_NONE);

    cudaFuncSetAttribute(lstm_persistent_kernel,
                         cudaFuncAttributeMaxDynamicSharedMemorySize, SMEM_BYTES);

    init_kernel<<<1, 256>>>();
    lstm_persistent_kernel<<<GRID, NT, SMEM_BYTES>>>(
        strokes, W_ih, W_hh, b_ih, b_hh, W_out, b_out, out, tmA, tmB);
}

// round 15
// speedup vs baseline: 2.1252x; 1.0833x over previous
#include <cuda_runtime.h>
#include <cuda.h>
#include <cuda_bf16.h>
#include <cstdint>

// Problem dims
#define BATCH 256
#define HID   512
#define SEQ   250
#define INDIM 5

// Tiling: 128 CTAs = 8 row-groups (M=32) x 16 col-slices (HC=32 units -> NC=128 gate rows).
// Broadcast traffic = 16 slices x 256KB = 4 MB/step (4x less than R14).
#define GRID  128
#define NT    256          // 8 warps: warp w -> m16 band (w&1), j-octet (w>>1)
#define HC 32
#define NC 128             // 4 gates * HC (W rows per CTA)

#define BP 520             // W tile pitch (bf16); 1040B rows -> conflict-free ldmatrix

// A tile: 8 regions of [32 rows x 128 B], TMA SW128-swizzled. 32768 B total.
#define SA_BYTES   32768
#define OFF_SBH    SA_BYTES
#define SBH_BYTES  (NC * BP * 2)                 // 133120
#define OFF_SWIH   (OFF_SBH + SBH_BYTES)
#define OFF_SBIAS  (OFF_SWIH + NC * INDIM * 4)
#define OFF_MBAR   (OFF_SBIAS + NC * 4)          // 4 mbarriers, 8B each
#define OFF_RED    (OFF_MBAR + 64)
#define SMEM_BYTES (OFF_RED + 64 + 1024)         // +1024 slack for in-kernel 1KB alignment

// Persistent state (device globals: no allocation in kernel_launch)
__device__ __nv_bfloat16 g_h[2][BATCH * HID];
// 8 independent row-group barriers (16 CTAs each); every counter/flag line-isolated.
__device__ unsigned g_sub[8][4][32];             // 4 sub-counters (4 CTAs each)
__device__ unsigned g_root[8][32];
__device__ unsigned g_gen[8][32];

__device__ __forceinline__ float fast_ex2(float x) {
    float y; asm("ex2.approx.f32 %0, %1;" : "=f"(y) : "f"(x)); return y;
}
__device__ __forceinline__ float fast_rcp(float x) {
    float y; asm("rcp.approx.f32 %0, %1;" : "=f"(y) : "f"(x)); return y;
}
__device__ __forceinline__ float fast_sig(float x) {
    return fast_rcp(1.0f + fast_ex2(-1.4426950408889634f * x));
}
__device__ __forceinline__ float fast_tanh(float x) {
    float s = fast_rcp(1.0f + fast_ex2(-2.8853900817779268f * x));
    return fmaf(2.0f, s, -1.0f);
}

__device__ __forceinline__ unsigned atom_add_acqrel(unsigned* p, unsigned v) {
    unsigned old;
    asm volatile("atom.add.acq_rel.gpu.u32 %0, [%1], %2;"
                 : "=r"(old) : "l"(p), "r"(v) : "memory");
    return old;
}

__device__ __forceinline__ void mma_bf16(float* c, const unsigned* a, unsigned b0, unsigned b1) {
    asm volatile(
        "mma.sync.aligned.m16n8k16.row.col.f32.bf16.bf16.f32 "
        "{%0,%1,%2,%3}, {%4,%5,%6,%7}, {%8,%9}, {%0,%1,%2,%3};"
        : "+f"(c[0]), "+f"(c[1]), "+f"(c[2]), "+f"(c[3])
        : "r"(a[0]), "r"(a[1]), "r"(a[2]), "r"(a[3]), "r"(b0), "r"(b1));
}

__device__ __forceinline__ void ldsm_x4(unsigned& r0, unsigned& r1, unsigned& r2, unsigned& r3,
                                        uint32_t addr) {
    asm volatile("ldmatrix.sync.aligned.m8n8.x4.shared.b16 {%0,%1,%2,%3}, [%4];"
                 : "=r"(r0), "=r"(r1), "=r"(r2), "=r"(r3) : "r"(addr));
}

// Warp-converged mbarrier parity wait (HW sleep, no CTA sync needed).
__device__ __forceinline__ void mbar_wait(uint32_t mbar, unsigned parity) {
    asm volatile(
        "{\n\t.reg .pred p;\n\t"
        "WAIT_%=:\n\t"
        "mbarrier.try_wait.parity.acquire.cta.shared::cta.b64 p, [%0], %1, 0x989680;\n\t"
        "@p bra.uni DONE_%=;\n\t"
        "bra.uni WAIT_%=;\n\t"
        "DONE_%=:\n\t}"
        :: "r"(mbar), "r"(parity) : "memory");
}

__global__ void init_kernel() {
    unsigned* s = &g_sub[0][0][0];
    for (int i = threadIdx.x; i < 8 * 4 * 32; i += blockDim.x) s[i] = 0u;
    for (int i = threadIdx.x; i < 8 * 32; i += blockDim.x) (&g_root[0][0])[i] = 0u;
    for (int i = threadIdx.x; i < 8 * 32; i += blockDim.x) (&g_gen[0][0])[i] = 0u;
}

__global__ __launch_bounds__(NT)
void lstm_persistent_kernel(const float* __restrict__ strokes,
                            const float* __restrict__ W_ih,
                            const float* __restrict__ W_hh,
                            const float* __restrict__ b_ih,
                            const float* __restrict__ b_hh,
                            const float* __restrict__ W_out,
                            const float* __restrict__ b_out,
                            float* __restrict__ out,
                            const __grid_constant__ CUtensorMap tmapA,   // g_h[0]
                            const __grid_constant__ CUtensorMap tmapB) { // g_h[1]
    extern __shared__ char smem_raw[];
    // Align the A tile to 1KB so the SW128 swizzle pattern matches TMA's (abs-addr bits).
    uint32_t raw = (uint32_t)__cvta_generic_to_shared(smem_raw);
    const uint32_t sa_base = (raw + 1023u) & ~1023u;
    char* base_ptr = smem_raw + (sa_base - raw);

    __nv_bfloat16* sBh   = (__nv_bfloat16*)(base_ptr + OFF_SBH);
    float*         swih  = (float*)(base_ptr + OFF_SWIH);
    float*         sbias = (float*)(base_ptr + OFF_SBIAS);
    const uint32_t mb_base = sa_base + OFF_MBAR;
    const uint32_t sbh_base = sa_base + OFF_SBH;

    const int tid = threadIdx.x;
    const int g = blockIdx.x >> 4;                 // row-group 0..7
    const int q = blockIdx.x & 15;                 // col-slice 0..15
    const int rowBase = g * 32;
    const int jBase = q * HC;                      // hidden-unit base (32 units)

    // ---- One-time: W_hh slice -> bf16 in [j-oct][gate][j&7] row order, W_ih, biases ----
    // smem row n = joct*32 + gate*8 + jl  <->  W_hh row gate*HID + jBase + joct*8 + jl
    #pragma unroll
    for (int it = 0; it < 64; it++) {
        int idx = tid + it * NT;                    // 16384 float4 (128 rows x 128)
        int n = idx >> 7, c = idx & 127;
        int joct = n >> 5, gate = (n >> 3) & 3, jl = n & 7;
        const float4* src = (const float4*)(W_hh + (size_t)(gate * HID + jBase + joct * 8 + jl) * HID);
        float4 v = src[c];
        __nv_bfloat16* dh = sBh + n * BP + c * 4;
        dh[0] = __float2bfloat16(v.x); dh[1] = __float2bfloat16(v.y);
        dh[2] = __float2bfloat16(v.z); dh[3] = __float2bfloat16(v.w);
    }
    if (tid < NC) {
        int joct = tid >> 5, gate = (tid >> 3) & 3, jl = tid & 7;
        int gr = gate * HID + jBase + joct * 8 + jl;
        sbias[tid] = b_ih[gr] + b_hh[gr];
        #pragma unroll
        for (int i = 0; i < INDIM; i++) swih[tid * INDIM + i] = W_ih[gr * INDIM + i];
    }
    if (tid == 0) {
        #pragma unroll
        for (int s = 0; s < 4; s++)
            asm volatile("mbarrier.init.shared.b64 [%0], %1;"
                         :: "r"(mb_base + s * 8), "r"(1u) : "memory");
    }
    __syncthreads();

    const int warp = tid >> 5, lane = tid & 31;
    const int g4 = lane >> 2, tg = lane & 3;
    const int band = (warp & 1) * 16;              // m16 band within the 32-row group
    const int wq = warp >> 1;                      // j-octet 0..3
    const int wBiasBase = wq * 32;                 // this warp's base into sbias/swih

    // ---- A-fragment addressing (TMA SW128, 32-row regions of 4096 B) ----
    const int lg = lane >> 3, lr = lane & 7;
    const int arow = band + (lg & 1) * 8 + lr;     // 0..31
    const uint32_t aLaneBase = sa_base + (uint32_t)arow * 128u;
    const uint32_t aXor = (uint32_t)((arow & 7) * 16);
    const uint32_t aKlg = (uint32_t)((lg >> 1) * 16);

    // B tiles: this warp's 32 W rows at sbh + wq*32*BP*2; within: rows 0-15 = gates i,f;
    // rows 16-31 = gates g,o (layout above). Same per-warp code as R14.
    const uint32_t bOff = (uint32_t)(((lg >> 1) * 8 + lr) * BP + (lg & 1) * 8) * 2;
    const uint32_t wB = (uint32_t)(wq * 32 * BP * 2);
    const uint32_t bhAddr0 = sbh_base + wB + bOff;
    const uint32_t bhAddr1 = sbh_base + wB + (uint32_t)(16 * BP * 2) + bOff;

    // c state in registers; x rows in registers (strokes immutable -> plain LDG safe)
    float c_reg[2][2] = {{0.0f, 0.0f}, {0.0f, 0.0f}};
    const float* xPtr0 = strokes + (size_t)(rowBase + band + g4) * (SEQ * INDIM);
    const float* xPtr1 = xPtr0 + (size_t)8 * (SEQ * INDIM);
    float xv0[INDIM], xv1[INDIM];
    #pragma unroll
    for (int i = 0; i < INDIM; i++) { xv0[i] = xPtr0[i]; xv1[i] = xPtr1[i]; }   // t=0

    for (int t = 0; t < SEQ; ++t) {
        // ---- x-projection from registers (while TMA chunks stream in) ----
        float xs[2][2][4];
        #pragma unroll
        for (int half = 0; half < 2; half++) {
            const float* xv = half ? xv1 : xv0;
            #pragma unroll
            for (int bb = 0; bb < 2; bb++) {
                const int j = 2 * tg + bb;
                #pragma unroll
                for (int gate = 0; gate < 4; gate++) {
                    const int n = wBiasBase + gate * 8 + j;
                    float s = sbias[n];
                    #pragma unroll
                    for (int i = 0; i < INDIM; i++) s += xv[i] * swih[n * INDIM + i];
                    xs[half][bb][gate] = s;
                }
            }
        }
        if (t + 1 < SEQ) {                          // prefetch x for t+1
            const float* n0 = xPtr0 + (t + 1) * INDIM;
            const float* n1 = xPtr1 + (t + 1) * INDIM;
            #pragma unroll
            for (int i = 0; i < INDIM; i++) { xv0[i] = n0[i]; xv1[i] = n1[i]; }
        }

        float acc[4][4];
        #pragma unroll
        for (int a = 0; a < 4; a++)
            #pragma unroll
            for (int b = 0; b < 4; b++) acc[a][b] = 0.0f;

        if (t > 0) {
            // ---- MMA over 4 TMA quarters; warp-local mbarrier waits, no CTA syncs ----
            const unsigned par = (unsigned)((t - 1) & 1);
            #pragma unroll
            for (int ch = 0; ch < 4; ch++) {
                mbar_wait(mb_base + ch * 8, par);
                #pragma unroll
                for (int i = 0; i < 8; i++) {
                    const int k0 = ch * 128 + i * 16;
                    const uint32_t aAddr = aLaneBase + (uint32_t)(k0 >> 6) * 4096u
                                         + (((uint32_t)((k0 & 63) * 2) | aKlg) ^ aXor);
                    const uint32_t kb = (uint32_t)(k0 * 2);
                    unsigned a[4], bh0[4], bh1[4];
                    ldsm_x4(a[0], a[1], a[2], a[3], aAddr);
                    ldsm_x4(bh0[0], bh0[1], bh0[2], bh0[3], bhAddr0 + kb);
                    ldsm_x4(bh1[0], bh1[1], bh1[2], bh1[3], bhAddr1 + kb);
                    mma_bf16(acc[0], a, bh0[0], bh0[1]);
                    mma_bf16(acc[1], a, bh0[2], bh0[3]);
                    mma_bf16(acc[2], a, bh1[0], bh1[1]);
                    mma_bf16(acc[3], a, bh1[2], bh1[3]);
                }
            }
        }

        // ---- Epilogue: gates -> c/h update (c in regs), packed bf16x2 h store ----
        __nv_bfloat16* __restrict__ hout = g_h[(t & 1) ^ 1];
        #pragma unroll
        for (int half = 0; half < 2; half++) {
            const int grow = rowBase + band + g4 + half * 8;
            __nv_bfloat16 hv[2];
            #pragma unroll
            for (int bb = 0; bb < 2; bb++) {
                const int e = half * 2 + bb;
                float iv = acc[0][e] + xs[half][bb][0];
                float fv = acc[1][e] + xs[half][bb][1];
                float gv = acc[2][e] + xs[half][bb][2];
                float ov = acc[3][e] + xs[half][bb][3];
                float cn = fast_sig(fv) * c_reg[half][bb] + fast_sig(iv) * fast_tanh(gv);
                c_reg[half][bb] = cn;
                hv[bb] = __float2bfloat16(fast_sig(ov) * fast_tanh(cn));
            }
            __nv_bfloat162 pack;
            pack.x = hv[0]; pack.y = hv[1];
            *(__nv_bfloat162*)(hout + (size_t)grow * HID + jBase + wq * 8 + 2 * tg) = pack;
        }

        // (a) all warps' h stores precede the arrival; (b) all smem A reads of step t
        // are done before TMA t+1 overwrites sA.
        __syncthreads();

        // ---- tid0: group barrier (16 CTAs, 4 sub x 4) arrive + poll, then TMA t+1 ----
        if (tid == 0) {
            unsigned a = atom_add_acqrel(&g_sub[g][q >> 2][0], 1u);
            if ((a & 3u) == 3u) {
                unsigned r = atom_add_acqrel(&g_root[g][0], 1u);
                if ((r & 3u) == 3u) {
                    asm volatile("st.release.gpu.u32 [%0], %1;"
                                 :: "l"(&g_gen[g][0]), "r"((unsigned)(t + 1)) : "memory");
                }
            }
            const unsigned target = (unsigned)(t + 1);
            unsigned v;
            do {
                asm volatile("ld.acquire.gpu.u32 %0, [%1];"
                             : "=r"(v) : "l"(&g_gen[g][0]) : "memory");
            } while (v < target);
            asm volatile("fence.proxy.async;" ::: "memory");
            if (t + 1 < SEQ) {
                const void* mp = ((t + 1) & 1) ? (const void*)&tmapB : (const void*)&tmapA;
                #pragma unroll
                for (int ch = 0; ch < 4; ch++) {
                    const uint32_t mb = mb_base + ch * 8;
                    asm volatile("mbarrier.arrive.expect_tx.shared.b64 _, [%0], %1;"
                                 :: "r"(mb), "r"(8192u) : "memory");
                    asm volatile(
                        "cp.async.bulk.tensor.2d.shared::cta.global.tile.mbarrier::complete_tx::bytes "
                        "[%0], [%1, {%2, %3}], [%4];"
                        :: "r"(sa_base + (uint32_t)(2 * ch) * 4096u), "l"(mp),
                           "r"(2 * ch * 128), "r"(rowBase), "r"(mb) : "memory");
                    asm volatile(
                        "cp.async.bulk.tensor.2d.shared::cta.global.tile.mbarrier::complete_tx::bytes "
                        "[%0], [%1, {%2, %3}], [%4];"
                        :: "r"(sa_base + (uint32_t)(2 * ch + 1) * 4096u), "l"(mp),
                           "r"((2 * ch + 1) * 128), "r"(rowBase), "r"(mb) : "memory");
                }
            }
        }
        if (warp == 0) __syncwarp();               // reconverge warp 0 before ldmatrix
    }

    __syncthreads();                               // own group's gen==SEQ: its 32 rows final

    // ---- Fused head: CTA bx -> batch rows 2bx, 2bx+1 (rows of THIS group). ----
    float* red = (float*)(base_ptr + OFF_RED);
    {
        const int r = (blockIdx.x << 1) + (tid >> 7);
        const int cb = (tid & 127) * 4;
        const __nv_bfloat16* hp = g_h[0] + (size_t)r * HID + cb;   // SEQ even -> final in buf 0
        uint2 v = __ldcg((const uint2*)hp);        // L1-bypass for coherence
        __nv_bfloat162 p0 = *reinterpret_cast<__nv_bfloat162*>(&v.x);
        __nv_bfloat162 p1 = *reinterpret_cast<__nv_bfloat162*>(&v.y);
        float s = __bfloat162float(p0.x) * W_out[cb]
                + __bfloat162float(p0.y) * W_out[cb + 1]
                + __bfloat162float(p1.x) * W_out[cb + 2]
                + __bfloat162float(p1.y) * W_out[cb + 3];
        #pragma unroll
        for (int o = 16; o; o >>= 1) s += __shfl_xor_sync(0xffffffffu, s, o);
        if (lane == 0) red[warp] = s;
    }
    __syncthreads();
    if (tid < 2) {
        float s = red[tid * 4] + red[tid * 4 + 1] + red[tid * 4 + 2] + red[tid * 4 + 3] + b_out[0];
        float lr = s > 0.0f ? s : 0.1f * s;
        out[(blockIdx.x << 1) + tid] = fast_sig(lr);
    }
}

typedef CUresult (CUDAAPI *PFN_encodeTiled_t)(
    CUtensorMap*, CUtensorMapDataType, cuuint32_t, void*,
    const cuuint64_t*, const cuuint64_t*, const cuuint32_t*, const cuuint32_t*,
    CUtensorMapInterleave, CUtensorMapSwizzle, CUtensorMapL2promotion, CUtensorMapFloatOOBfill);

extern "C" void kernel_launch(void* const* d_in, const int* in_sizes, int n_in,
                              void* d_out, int out_size) {
    const float* strokes = (const float*)d_in[0];
    const float* W_ih    = (const float*)d_in[1];
    const float* W_hh    = (const float*)d_in[2];
    const float* b_ih    = (const float*)d_in[3];
    const float* b_hh    = (const float*)d_in[4];
    const float* W_out   = (const float*)d_in[5];
    const float* b_out   = (const float*)d_in[6];
    float* out = (float*)d_out;

    PFN_encodeTiled_t pfn = nullptr;
    cudaDriverEntryPointQueryResult st;
#if CUDART_VERSION >= 12050
    cudaGetDriverEntryPointByVersion("cuTensorMapEncodeTiled", (void**)&pfn, 12000,
                                     cudaEnableDefault, &st);
#else
    cudaGetDriverEntryPoint("cuTensorMapEncodeTiled", (void**)&pfn, cudaEnableDefault, &st);
#endif
    void* ghp = nullptr;
    cudaGetSymbolAddress(&ghp, g_h);

    CUtensorMap tmA, tmB;
    cuuint64_t gd[2] = {1024ull, 256ull};     // bytes per row, rows (uint8 view)
    cuuint64_t gs[1] = {1024ull};             // row stride in bytes
    cuuint32_t bx[2] = {128u, 32u};           // 128B x 32-row box (SW128)
    cuuint32_t es[2] = {1u, 1u};
    pfn(&tmA, CU_TENSOR_MAP_DATA_TYPE_UINT8, 2, ghp, gd, gs, bx, es,
        CU_TENSOR_MAP_INTERLEAVE_NONE, CU_TENSOR_MAP_SWIZZLE_128B,
        CU_TENSOR_MAP_L2_PROMOTION_L2_128B, CU_TENSOR_MAP_FLOAT_OOB_FILL_NONE);
    pfn(&tmB, CU_TENSOR_MAP_DATA_TYPE_UINT8, 2, (void*)((char*)ghp + (size_t)BATCH * HID * 2),
        gd, gs, bx, es,
        CU_TENSOR_MAP_INTERLEAVE_NONE, CU_TENSOR_MAP_SWIZZLE_128B,
        CU_TENSOR_MAP_L2_PROMOTION_L2_128B, CU_TENSOR_MAP_FLOAT_OOB_FILL_NONE);

    cudaFuncSetAttribute(lstm_persistent_kernel,
                         cudaFuncAttributeMaxDynamicSharedMemorySize, SMEM_BYTES);

    init_kernel<<<1, 256>>>();
    lstm_persistent_kernel<<<GRID, NT, SMEM_BYTES>>>(
        strokes, W_ih, W_hh, b_ih, b_hh, W_out, b_out, out, tmA, tmB);
}